// round 9
// baseline (speedup 1.0000x reference)
#include <cuda_runtime.h>

#define BATCH 16
#define HH 512
#define WW 512
#define HWSZ (HH * WW)
#define TR 8
#define NBLK 1024             // MUST be <= 148 * 8 resident capacity (it is: 1184)

// ---- scratch (no allocations allowed; zero-initialized at module load) ----
__device__ float g_colsum[BATCH][WW];   // de_h summed over H, per column ([0..510] used)
__device__ float g_rowsum[BATCH][HH];   // de_v summed over W, per row    ([0..510] + phantom 511)
__device__ unsigned int g_arrive;       // global-barrier arrival counter
__device__ unsigned int g_exit;         // exit ticket counter (last block cleans up)

__device__ __forceinline__ float lum1(const float* p) {
    return 0.299f * p[0] + 0.587f * p[HWSZ] + 0.114f * p[2 * HWSZ];
}
__device__ __forceinline__ float2 lum2(float2 c0, float2 c1, float2 c2) {
    float2 l;
    l.x = 0.299f * c0.x + 0.587f * c1.x + 0.114f * c2.x;
    l.y = 0.299f * c0.y + 0.587f * c1.y + 0.114f * c2.y;
    return l;
}
// clipped excess: max(|t0-t1| - |r0-r1|, 0)
__device__ __forceinline__ float dexc(float t0, float t1, float r0, float r1) {
    return fmaxf(fabsf(t0 - t1) - fabsf(r0 - r1), 0.0f);
}

// -------------------------------------------------------------------------
// Single fused persistent kernel.
//  Phase 1: accumulation — IDENTICAL to the proven R6 strip kernel
//           (warp = 64-col x 8-row strip, float2/lane, barrier-free).
//  Global barrier: arrive-counter + spin (all 1024 blocks co-resident by
//           __launch_bounds__(256,8): capacity 1184 >= 1024 -> no deadlock).
//  Phase 2: each block computes its batch's phase decision from L2.
//  Phase 3: each block writes its 8-row x 512-col slice of the mask.
//  Exit:    last block (ticket) zeroes accumulators + counters so every
//           graph replay is identical and deterministic.
// -------------------------------------------------------------------------
__global__ __launch_bounds__(256, 8) void jb_fused_kernel(
    const float* __restrict__ ref, const float* __restrict__ tgt,
    float* __restrict__ out)
{
    const int wid   = threadIdx.x >> 5;
    const int lane  = threadIdx.x & 31;
    const int t     = threadIdx.x;
    const int b     = blockIdx.x >> 6;    // 64 blocks per batch

    // ================= Phase 1: accumulation (R6 body) =================
    {
        const int gw    = blockIdx.x * 8 + wid;
        const int rem   = gw & 511;
        const int tile  = rem >> 3;
        const int strip = rem & 7;
        const int r0    = tile * TR;
        const int c0    = strip * 64 + lane * 2;

        const float* rB = ref + (size_t)b * 3 * HWSZ;
        const float* tB = tgt + (size_t)b * 3 * HWSZ;

        const bool bnd_load = (lane == 31) && (strip < 7);
        const bool bnd_skip = (lane == 31) && (strip == 7);

        float2 cacc = make_float2(0.f, 0.f);
        float2 plr, plt;

        #pragma unroll 3
        for (int i = 0; i <= TR; ++i) {
            const int r = min(r0 + i, HH - 1);       // clamp phantom row
            const float* rp = rB + (size_t)r * WW + c0;
            const float* tp = tB + (size_t)r * WW + c0;
            float2 rc0 = *reinterpret_cast<const float2*>(rp);
            float2 rc1 = *reinterpret_cast<const float2*>(rp + HWSZ);
            float2 rc2 = *reinterpret_cast<const float2*>(rp + 2 * HWSZ);
            float2 tc0 = *reinterpret_cast<const float2*>(tp);
            float2 tc1 = *reinterpret_cast<const float2*>(tp + HWSZ);
            float2 tc2 = *reinterpret_cast<const float2*>(tp + 2 * HWSZ);
            float2 lr = lum2(rc0, rc1, rc2);
            float2 lt = lum2(tc0, tc1, tc2);

            if (i < TR) {
                float nr = __shfl_down_sync(0xffffffffu, lr.x, 1);
                float nt = __shfl_down_sync(0xffffffffu, lt.x, 1);
                if (bnd_load) {
                    nr = lum1(rp + 2);
                    nt = lum1(tp + 2);
                }
                cacc.x += dexc(lt.x, lt.y, lr.x, lr.y);
                if (!bnd_skip)
                    cacc.y += dexc(lt.y, nt, lr.y, nr);
            }

            if (i > 0) {
                float dv = dexc(plt.x, lt.x, plr.x, lr.x)
                         + dexc(plt.y, lt.y, plr.y, lr.y);
                #pragma unroll
                for (int off = 16; off > 0; off >>= 1)
                    dv += __shfl_down_sync(0xffffffffu, dv, off);
                if (lane == 0)
                    atomicAdd(&g_rowsum[b][r0 + i - 1], dv);  // phantom -> idx 511 (unused)
            }
            plr = lr; plt = lt;
        }

        atomicAdd(&g_colsum[b][c0 + 0], cacc.x);
        atomicAdd(&g_colsum[b][c0 + 1], cacc.y);
    }

    // ================= Global barrier =================
    __syncthreads();
    if (t == 0) {
        __threadfence();                        // accum atomics before arrival
        atomicAdd(&g_arrive, 1u);
        while (*(volatile unsigned int*)&g_arrive < NBLK)
            __nanosleep(64);
    }
    __syncthreads();
    __threadfence();                            // acquire side

    // ================= Phase 2: per-batch phase decision =================
    __shared__ float ph[2][8];
    __shared__ int   dec[4];                    // kh, bh, kv, bv
    if (t < 16) ph[t >> 3][t & 7] = 0.0f;
    __syncthreads();

    if (t < 128) {
        const int grp = t >> 6;                 // 0 = h (cols), 1 = v (rows)
        const int i0  = t & 63;
        const float* src = grp ? g_rowsum[b] : g_colsum[b];
        float acc = 0.0f;
        for (int i = i0; i < 511; i += 64)
            acc += src[i] * (1.0f / 512.0f);    // line mean
        atomicAdd(&ph[grp][i0 & 7], acc);
    }
    __syncthreads();

    if (t < 2) {
        float total = 0.0f;
        #pragma unroll
        for (int k = 0; k < 8; ++k) total += ph[t][k];
        float best_r = -1.0f;
        int   best_k = 0;
        #pragma unroll
        for (int k = 0; k < 8; ++k) {
            float cnt   = (k < 7) ? 64.0f : 63.0f;   // 511 lines: phases 0..6 have 64
            float a_k   = ph[t][k] / cnt;
            float bg    = (total - ph[t][k]) / (511.0f - cnt);
            float ratio = a_k / (bg + 1e-8f);
            if (ratio > best_r) { best_r = ratio; best_k = k; }  // first-max (argmax)
        }
        dec[t * 2 + 0] = best_k;
        dec[t * 2 + 1] = best_r > (1.0f / 0.35f);
    }
    __syncthreads();

    // ================= Phase 3: write this block's 8-row slice =================
    {
        const int kh = dec[0], bh = dec[1];
        const int kv = dec[2], bv = dec[3];
        const int rem_blk = blockIdx.x & 63;
        const int row = rem_blk * 8 + (t >> 5);      // 8 rows, 32 threads each
        const int cg  = t & 31;                      // 16-col chunk
        const bool vrow = bv && ((row & 7) == kv) && (row < HH - 1);
        const bool tail = (cg == 31);                // chunk containing col 511

        float4 o[4];
        float* op = reinterpret_cast<float*>(o);
        #pragma unroll
        for (int j = 0; j < 16; ++j) {
            bool vcol = bh && ((j & 7) == kh) && !(tail && j == 15);
            op[j] = (vrow || vcol) ? 1.0f : 0.0f;
        }
        float4* dst = reinterpret_cast<float4*>(
            out + ((size_t)b * HH + row) * WW + cg * 16);
        dst[0] = o[0]; dst[1] = o[1]; dst[2] = o[2]; dst[3] = o[3];
    }

    // ================= Exit: last block cleans scratch for next replay ===
    __syncthreads();
    __shared__ unsigned int s_ticket;
    if (t == 0) {
        __threadfence();                        // my reads of col/rowsum are done
        s_ticket = atomicAdd(&g_exit, 1u) + 1u;
    }
    __syncthreads();
    if (s_ticket == NBLK) {                     // all blocks finished reading
        for (int i = t; i < BATCH * WW; i += 256) {
            (&g_colsum[0][0])[i] = 0.0f;
            (&g_rowsum[0][0])[i] = 0.0f;
        }
        __syncthreads();
        if (t == 0) {
            g_arrive = 0;
            g_exit   = 0;
            __threadfence();
        }
    }
}

// -------------------------------------------------------------------------
extern "C" void kernel_launch(void* const* d_in, const int* in_sizes, int n_in,
                              void* d_out, int out_size)
{
    const float* ref = (const float*)d_in[0];
    const float* tgt = (const float*)d_in[1];
    float* out = (float*)d_out;

    jb_fused_kernel<<<NBLK, 256>>>(ref, tgt, out);
}

// round 10
// speedup vs baseline: 1.2469x; 1.2469x over previous
#include <cuda_runtime.h>

#define BATCH 16
#define HH 512
#define WW 512
#define HWSZ (HH * WW)
#define TR 8

// ---- scratch (no allocations allowed; zero-initialized at module load) ----
__device__ float g_colsum[BATCH][WW];    // de_h summed over H, per column ([0..510] used)
__device__ float g_rowsum[BATCH][HH];    // de_v summed over W, per row ([0..510] + phantom 511)
__device__ unsigned int g_done[BATCH];   // per-batch writer-completion tickets

__device__ __forceinline__ float lum1(const float* p) {
    return 0.299f * p[0] + 0.587f * p[HWSZ] + 0.114f * p[2 * HWSZ];
}
__device__ __forceinline__ float2 lum2(float2 c0, float2 c1, float2 c2) {
    float2 l;
    l.x = 0.299f * c0.x + 0.587f * c1.x + 0.114f * c2.x;
    l.y = 0.299f * c0.y + 0.587f * c1.y + 0.114f * c2.y;
    return l;
}
// clipped excess: max(|t0-t1| - |r0-r1|, 0)
__device__ __forceinline__ float dexc(float t0, float t1, float r0, float r1) {
    return fmaxf(fabsf(t0 - t1) - fabsf(r0 - r1), 0.0f);
}

// -------------------------------------------------------------------------
// Kernel 1: barrier-free streaming reduction (UNCHANGED from the proven
// 22.5us version). Warp = 64-col x TR-row strip, float2 per lane.
// grid: BATCH * 64 tiles * 8 strips = 8192 warps, 8 warps/block.
// -------------------------------------------------------------------------
__global__ __launch_bounds__(256) void jb_accum_kernel(
    const float* __restrict__ ref, const float* __restrict__ tgt)
{
    const int gw    = blockIdx.x * 8 + (threadIdx.x >> 5);
    const int lane  = threadIdx.x & 31;
    const int b     = gw >> 9;            // 512 warps per batch
    const int rem   = gw & 511;
    const int tile  = rem >> 3;
    const int strip = rem & 7;
    const int r0    = tile * TR;
    const int c0    = strip * 64 + lane * 2;

    const float* rB = ref + (size_t)b * 3 * HWSZ;
    const float* tB = tgt + (size_t)b * 3 * HWSZ;

    const bool bnd_load = (lane == 31) && (strip < 7);   // col c0+2 in next strip
    const bool bnd_skip = (lane == 31) && (strip == 7);  // col 511: no right neighbor

    float2 cacc = make_float2(0.f, 0.f);
    float2 plr, plt;

    #pragma unroll 3
    for (int i = 0; i <= TR; ++i) {
        const int r = min(r0 + i, HH - 1);       // clamp phantom row
        const float* rp = rB + (size_t)r * WW + c0;
        const float* tp = tB + (size_t)r * WW + c0;
        float2 rc0 = *reinterpret_cast<const float2*>(rp);
        float2 rc1 = *reinterpret_cast<const float2*>(rp + HWSZ);
        float2 rc2 = *reinterpret_cast<const float2*>(rp + 2 * HWSZ);
        float2 tc0 = *reinterpret_cast<const float2*>(tp);
        float2 tc1 = *reinterpret_cast<const float2*>(tp + HWSZ);
        float2 tc2 = *reinterpret_cast<const float2*>(tp + 2 * HWSZ);
        float2 lr = lum2(rc0, rc1, rc2);
        float2 lt = lum2(tc0, tc1, tc2);

        if (i < TR) {
            float nr = __shfl_down_sync(0xffffffffu, lr.x, 1);
            float nt = __shfl_down_sync(0xffffffffu, lt.x, 1);
            if (bnd_load) {                  // boundary luminance (col c0+2)
                nr = lum1(rp + 2);
                nt = lum1(tp + 2);
            }
            cacc.x += dexc(lt.x, lt.y, lr.x, lr.y);
            if (!bnd_skip)
                cacc.y += dexc(lt.y, nt, lr.y, nr);
        }

        if (i > 0) {
            float dv = dexc(plt.x, lt.x, plr.x, lr.x)
                     + dexc(plt.y, lt.y, plr.y, lr.y);
            #pragma unroll
            for (int off = 16; off > 0; off >>= 1)
                dv += __shfl_down_sync(0xffffffffu, dv, off);
            if (lane == 0)
                atomicAdd(&g_rowsum[b][r0 + i - 1], dv);  // phantom -> idx 511 (unused)
        }
        plr = lr; plt = lt;
    }

    atomicAdd(&g_colsum[b][c0 + 0], cacc.x);
    atomicAdd(&g_colsum[b][c0 + 1], cacc.y);
}

// -------------------------------------------------------------------------
// Kernel 2 (fused decide + write): each block redundantly computes its
// batch's phase decision from the L2-resident line sums (4 KB), then
// writes its 16-row x 512-col slice of the mask (32 floats / thread).
// The LAST of a batch's 32 blocks (exit ticket) zeroes that batch's
// accumulators -> graph replays start clean; no global barrier.
// grid: BATCH * 32 = 512 blocks of 256 threads.
// -------------------------------------------------------------------------
__global__ __launch_bounds__(256) void jb_decide_write_kernel(float* __restrict__ out)
{
    const int b   = blockIdx.x >> 5;         // 32 blocks per batch
    const int blk = blockIdx.x & 31;         // slice index within batch
    const int t   = threadIdx.x;

    // ---- decision (threads 0..127; 0..63 cols/h, 64..127 rows/v) ----
    __shared__ float ph[2][8];
    __shared__ int   dec[4];                 // kh, bh, kv, bv
    if (t < 16) ph[t >> 3][t & 7] = 0.0f;
    __syncthreads();

    if (t < 128) {
        const int grp = t >> 6;
        const int i0  = t & 63;
        const float* src = grp ? g_rowsum[b] : g_colsum[b];
        float acc = 0.0f;
        #pragma unroll
        for (int i = i0; i < 511; i += 64)
            acc += src[i] * (1.0f / 512.0f); // line mean
        atomicAdd(&ph[grp][i0 & 7], acc);
    }
    __syncthreads();

    if (t < 2) {
        float total = 0.0f;
        #pragma unroll
        for (int k = 0; k < 8; ++k) total += ph[t][k];
        float best_r = -1.0f;
        int   best_k = 0;
        #pragma unroll
        for (int k = 0; k < 8; ++k) {
            float cnt   = (k < 7) ? 64.0f : 63.0f;   // 511 lines: phases 0..6 have 64
            float a_k   = ph[t][k] / cnt;
            float bg    = (total - ph[t][k]) / (511.0f - cnt);
            float ratio = a_k / (bg + 1e-8f);
            if (ratio > best_r) { best_r = ratio; best_k = k; }  // first-max (argmax)
        }
        dec[t * 2 + 0] = best_k;
        dec[t * 2 + 1] = best_r > (1.0f / 0.35f);
    }
    __syncthreads();

    // ---- write 16 rows: 256 threads x 32 floats (8 x STG.128) ----
    {
        const int kh = dec[0], bh = dec[1];
        const int kv = dec[2], bv = dec[3];
        const int row = blk * 16 + (t >> 4);     // 16 threads per row
        const int cg  = t & 15;                  // 32-col chunk
        const bool vrow = bv && ((row & 7) == kv) && (row < HH - 1);
        const bool tail = (cg == 15);            // chunk containing col 511

        float4 o[8];
        float* op = reinterpret_cast<float*>(o);
        #pragma unroll
        for (int j = 0; j < 32; ++j) {
            bool vcol = bh && ((j & 7) == kh) && !(tail && j == 31);
            op[j] = (vrow || vcol) ? 1.0f : 0.0f;
        }
        float4* dst = reinterpret_cast<float4*>(
            out + ((size_t)b * HH + row) * WW + cg * 32);
        #pragma unroll
        for (int j = 0; j < 8; ++j) dst[j] = o[j];
    }

    // ---- exit ticket: last block of this batch zeroes its accumulators ----
    __syncthreads();
    __shared__ unsigned int s_ticket;
    if (t == 0) {
        __threadfence();                     // my reads of the sums are complete
        s_ticket = atomicAdd(&g_done[b], 1u) + 1u;
    }
    __syncthreads();
    if (s_ticket == 32u) {                   // all 32 readers of batch b are done
        if (t < 128) {
            #pragma unroll
            for (int i = t; i < WW; i += 128) {
                g_colsum[b][i] = 0.0f;
                g_rowsum[b][i] = 0.0f;
            }
        }
        __syncthreads();
        if (t == 0) {
            g_done[b] = 0u;
            __threadfence();
        }
    }
}

// -------------------------------------------------------------------------
extern "C" void kernel_launch(void* const* d_in, const int* in_sizes, int n_in,
                              void* d_out, int out_size)
{
    const float* ref = (const float*)d_in[0];
    const float* tgt = (const float*)d_in[1];
    float* out = (float*)d_out;

    // 16 batches * 64 tiles * 8 strips = 8192 warps -> 1024 blocks of 8 warps
    jb_accum_kernel<<<1024, 256>>>(ref, tgt);

    // 16 batches * 32 row-slices
    jb_decide_write_kernel<<<512, 256>>>(out);
}